// round 4
// baseline (speedup 1.0000x reference)
#include <cuda_runtime.h>
#include <cuda_bf16.h>

// Problem constants
#define B    8
#define HIN  256
#define WIN  256
#define CV4  16      // C/4 float4 chunks per pixel (C=64)
#define HP   64
#define WP   64

// 8 MB pooled averages — static device scratch
__device__ float4 g_pooled[B * HP * WP * CV4];

__device__ __forceinline__ void acc4(float4& a, const float4 v) {
    a.x += v.x; a.y += v.y; a.z += v.z; a.w += v.w;
}
__device__ __forceinline__ float4 blend2(float4 p, float wp, float4 q, float wq) {
    float4 r;
    r.x = p.x * wp + q.x * wq;
    r.y = p.y * wp + q.y * wq;
    r.z = p.z * wp + q.z * wq;
    r.w = p.w * wp + q.w * wq;
    return r;
}

// ---------------------------------------------------------------------------
// K1: fused SAME avg-pool 6x6 stride 4 (separable via smem column sums).
// CTA = (b, oy, xhalf). Phase 1: column sums over the y-window for 130
// consecutive x positions into smem. Phase 2: row-pool windows of 6 + divide
// by valid count, write g_pooled. Traffic: input read once + 8 MB write.
// ---------------------------------------------------------------------------
#define XSPAN 130                 // 4*32 - 1 + 6 - 1 + ... = columns needed per half
#define NTASK1 (XSPAN * CV4)      // 2080 colsum tasks per CTA

__global__ __launch_bounds__(256) void pool_kernel(const float4* __restrict__ in4) {
    __shared__ float4 cs[NTASK1]; // [x_local][c4], 33.3 KB

    int bid = blockIdx.x;         // b*128 + oy*2 + xh
    int xh  = bid & 1;
    int oy  = (bid >> 1) & 63;
    int b   = bid >> 7;

    int oxbase = xh * 32;
    int xstart = 4 * oxbase - 1;  // global x of local 0
    int r0     = 4 * oy - 1;

    const float4* base = in4 + ((size_t)b * HIN * WIN) * CV4;
    bool y_interior = (oy != 0) && (oy != 63);

    // Phase 1: column sums
    #pragma unroll 1
    for (int w = threadIdx.x; w < NTASK1; w += 256) {
        int c4 = w & 15;
        int xl = w >> 4;
        int x  = xstart + xl;
        float4 s = make_float4(0.f, 0.f, 0.f, 0.f);
        if ((unsigned)x < 256u) {
            const float4* p = base + ((size_t)x) * CV4 + c4;
            if (y_interior) {
                const float4* q = p + (size_t)r0 * WIN * CV4;
                #pragma unroll
                for (int j = 0; j < 6; ++j)
                    acc4(s, __ldg(q + (size_t)j * WIN * CV4));
            } else {
                #pragma unroll
                for (int j = 0; j < 6; ++j) {
                    int r = r0 + j;
                    if ((unsigned)r < 256u)
                        acc4(s, __ldg(p + (size_t)r * WIN * CV4));
                }
            }
        }
        cs[w] = s;
    }
    __syncthreads();

    // Phase 2: row pool + divide. 32 ox * 16 c4 = 512 tasks.
    int nr = y_interior ? 6 : 5;
    #pragma unroll
    for (int w = threadIdx.x; w < 32 * CV4; w += 256) {
        int c4  = w & 15;
        int oxl = w >> 4;
        int ox  = oxbase + oxl;

        float4 s = make_float4(0.f, 0.f, 0.f, 0.f);
        // smem col index for window tap j: 4*oxl + j (global col 4*ox-1+j)
        #pragma unroll
        for (int j = 0; j < 6; ++j) {
            bool valid = !((ox == 0 && j == 0) || (ox == 63 && j == 5));
            if (valid) acc4(s, cs[(4 * oxl + j) * CV4 + c4]);
        }
        int nc = 6 - (ox == 0) - (ox == 63);
        float inv = 1.0f / (float)(nr * nc);
        g_pooled[(((size_t)b * HP + oy) * WP + ox) * CV4 + c4] =
            make_float4(s.x * inv, s.y * inv, s.z * inv, s.w * inv);
    }
}

// ---------------------------------------------------------------------------
// K2: unaverage pool (x4 upsample, reference's piecewise dest->source).
// One thread = 8 consecutive x outputs (two k-groups) x one float4 chunk.
// Taps: pooled cols k0-1..k0+2, rows r0,r0+1 -> 8 loads / 8 outputs.
// Interior kk (1..30): compile-time fc weights. y math uniform per CTA.
// ---------------------------------------------------------------------------
__device__ __forceinline__ float d2s(float d) {
    if (d < 5.5f)   return (d - 2.0f) * (1.0f / 3.5f);
    if (d > 249.5f) return (d - 249.5f) * (1.0f / 3.5f) + 62.0f;
    return (d - 1.5f) * 0.25f;
}

__global__ __launch_bounds__(256) void up_kernel(float4* __restrict__ out4) {
    int tid = blockIdx.x * 256 + threadIdx.x;   // B*256*32*16 = 1,048,576
    int c4 = tid & 15;
    int kk = (tid >> 4) & 31;
    int y  = (tid >> 9) & 255;
    int b  = tid >> 17;

    int k0 = kk * 2;

    // Row mapping (uniform per CTA)
    float sr  = d2s((float)y);
    float r0f = floorf(sr);
    int   r0  = (int)r0f;
    float fr  = sr - r0f;
    bool rv0 = (r0 >= 0);
    bool rv1 = (r0 < HP - 1);
    float wr0 = 1.0f - fr;

    const float4* pbase = g_pooled + ((size_t)b * HP * WP) * CV4 + c4;
    const float4* rowA  = pbase + (size_t)(rv0 ? r0     : 0) * WP * CV4;
    const float4* rowB  = pbase + (size_t)(rv1 ? r0 + 1 : 0) * WP * CV4;

    const float4 z = make_float4(0.f, 0.f, 0.f, 0.f);

    // 4 column taps, row-blended: T[i] = col k0-1+i
    float4 T[4];
    #pragma unroll
    for (int i = 0; i < 4; ++i) {
        int col = k0 - 1 + i;
        bool cv = (unsigned)col < (unsigned)WP;
        float4 a = (rv0 && cv) ? __ldg(rowA + (size_t)col * CV4) : z;
        float4 bb = (rv1 && cv) ? __ldg(rowB + (size_t)col * CV4) : z;
        T[i] = blend2(a, wr0, bb, fr);
    }

    float4* op = out4 + (((size_t)b * HIN + y) * WIN + k0 * 4) * CV4 + c4;

    if (kk >= 1 && kk <= 30) {
        // interior: constant weights
        op[0 * CV4] = blend2(T[0], 0.375f, T[1], 0.625f);
        op[1 * CV4] = blend2(T[0], 0.125f, T[1], 0.875f);
        op[2 * CV4] = blend2(T[1], 0.875f, T[2], 0.125f);
        op[3 * CV4] = blend2(T[1], 0.625f, T[2], 0.375f);
        op[4 * CV4] = blend2(T[1], 0.375f, T[2], 0.625f);
        op[5 * CV4] = blend2(T[1], 0.125f, T[2], 0.875f);
        op[6 * CV4] = blend2(T[2], 0.875f, T[3], 0.125f);
        op[7 * CV4] = blend2(T[2], 0.625f, T[3], 0.375f);
    } else {
        // boundary groups: generic mapping (x known at compile time per m
        // once kk resolves; only 2 warps/CTA take this path)
        int x0 = k0 * 4;
        #pragma unroll
        for (int m = 0; m < 8; ++m) {
            float sc  = d2s((float)(x0 + m));
            float c0f = floorf(sc);
            float fc  = sc - c0f;
            int idx = (int)c0f - (k0 - 1);   // 0..2
            float4 lo = (idx == 0) ? T[0] : ((idx == 1) ? T[1] : T[2]);
            float4 hi = (idx == 0) ? T[1] : ((idx == 1) ? T[2] : T[3]);
            op[m * CV4] = blend2(lo, 1.0f - fc, hi, fc);
        }
    }
}

extern "C" void kernel_launch(void* const* d_in, const int* in_sizes, int n_in,
                              void* d_out, int out_size) {
    const float4* in4 = (const float4*)d_in[0];
    float4* out4 = (float4*)d_out;

    pool_kernel<<<B * HP * 2, 256>>>(in4);             // 1024 CTAs
    up_kernel<<<(B * HIN * 32 * CV4) / 256, 256>>>(out4); // 4096 CTAs
}

// round 5
// speedup vs baseline: 1.2972x; 1.2972x over previous
#include <cuda_runtime.h>
#include <cuda_bf16.h>

// Problem constants
#define B    8
#define HIN  256
#define WIN  256
#define CV4  16      // C/4 float4 chunks per pixel (C=64)
#define HP   64
#define WP   64

// 8 MB pooled averages — static device scratch
__device__ float4 g_pooled[B * HP * WP * CV4];

__device__ __forceinline__ void acc4(float4& a, const float4 v) {
    a.x += v.x; a.y += v.y; a.z += v.z; a.w += v.w;
}
__device__ __forceinline__ float4 blend2(float4 p, float wp, float4 q, float wq) {
    float4 r;
    r.x = p.x * wp + q.x * wq;
    r.y = p.y * wp + q.y * wq;
    r.z = p.z * wp + q.z * wq;
    r.w = p.w * wp + q.w * wq;
    return r;
}

// ---------------------------------------------------------------------------
// K1: fused SAME avg-pool 6x6 stride 4, separable via tiny smem tile.
// Grid = 8192 CTAs (b x oy x ox-quad), block = 288 threads, smem = 4.6 KB.
// Phase 1: each thread = ONE column-sum task (x-col, c4): 6 strided loads
//          (same per-thread shape as the proven colpool kernel).
// Phase 2: 64 threads row-pool windows of 6 from smem + divide, 1 store.
// DRAM: input read once (134 MB) + 8 MB pooled write. No 33.5 MB round trip.
// ---------------------------------------------------------------------------
__global__ __launch_bounds__(288) void pool_kernel(const float4* __restrict__ in4) {
    __shared__ float4 cs[18 * CV4];   // [xl][c4]

    int bid = blockIdx.x;             // b*1024 + oy*16 + q
    int q  = bid & 15;
    int oy = (bid >> 4) & 63;
    int b  = bid >> 10;

    int t  = threadIdx.x;             // 0..287
    int c4 = t & 15;
    int xl = t >> 4;                  // 0..17
    int x  = 16 * q - 1 + xl;
    int r0 = 4 * oy - 1;

    // Phase 1: column sum over y-window
    float4 s = make_float4(0.f, 0.f, 0.f, 0.f);
    if ((unsigned)x < 256u) {
        const float4* p = in4 + (((size_t)b * HIN) * WIN + x) * CV4 + c4;
        if (oy != 0 && oy != 63) {
            const float4* qq = p + (size_t)r0 * WIN * CV4;
            #pragma unroll
            for (int j = 0; j < 6; ++j)
                acc4(s, __ldg(qq + (size_t)j * WIN * CV4));
        } else {
            #pragma unroll
            for (int j = 0; j < 6; ++j) {
                int r = r0 + j;
                if ((unsigned)r < 256u)
                    acc4(s, __ldg(p + (size_t)r * WIN * CV4));
            }
        }
    }
    cs[t] = s;
    __syncthreads();

    // Phase 2: row pool + divide (threads 0..63)
    if (t < 64) {
        int oxl = t >> 4;             // 0..3
        int ox  = 4 * q + oxl;

        // window taps: cs[(4*oxl + j)][c4], global col 4*ox-1+j
        float4 acc = make_float4(0.f, 0.f, 0.f, 0.f);
        if (ox != 0) acc4(acc, cs[(4 * oxl + 0) * CV4 + c4]);
        acc4(acc, cs[(4 * oxl + 1) * CV4 + c4]);
        acc4(acc, cs[(4 * oxl + 2) * CV4 + c4]);
        acc4(acc, cs[(4 * oxl + 3) * CV4 + c4]);
        acc4(acc, cs[(4 * oxl + 4) * CV4 + c4]);
        if (ox != 63) acc4(acc, cs[(4 * oxl + 5) * CV4 + c4]);

        int nr = 6 - (oy == 0) - (oy == 63);
        int nc = 6 - (ox == 0) - (ox == 63);
        float inv = 1.0f / (float)(nr * nc);
        g_pooled[(((size_t)b * HP + oy) * WP + ox) * CV4 + c4] =
            make_float4(acc.x * inv, acc.y * inv, acc.z * inv, acc.w * inv);
    }
}

// ---------------------------------------------------------------------------
// K2: unaverage pool (x4 upsample, reference's piecewise dest->source).
// One thread = 8 consecutive x outputs (two k-groups) x one float4 chunk.
// Validated at 23.7us (~write floor).
// ---------------------------------------------------------------------------
__device__ __forceinline__ float d2s(float d) {
    if (d < 5.5f)   return (d - 2.0f) * (1.0f / 3.5f);
    if (d > 249.5f) return (d - 249.5f) * (1.0f / 3.5f) + 62.0f;
    return (d - 1.5f) * 0.25f;
}

__global__ __launch_bounds__(256) void up_kernel(float4* __restrict__ out4) {
    int tid = blockIdx.x * 256 + threadIdx.x;   // B*256*32*16 = 1,048,576
    int c4 = tid & 15;
    int kk = (tid >> 4) & 31;
    int y  = (tid >> 9) & 255;
    int b  = tid >> 17;

    int k0 = kk * 2;

    float sr  = d2s((float)y);
    float r0f = floorf(sr);
    int   r0  = (int)r0f;
    float fr  = sr - r0f;
    bool rv0 = (r0 >= 0);
    bool rv1 = (r0 < HP - 1);
    float wr0 = 1.0f - fr;

    const float4* pbase = g_pooled + ((size_t)b * HP * WP) * CV4 + c4;
    const float4* rowA  = pbase + (size_t)(rv0 ? r0     : 0) * WP * CV4;
    const float4* rowB  = pbase + (size_t)(rv1 ? r0 + 1 : 0) * WP * CV4;

    const float4 z = make_float4(0.f, 0.f, 0.f, 0.f);

    float4 T[4];
    #pragma unroll
    for (int i = 0; i < 4; ++i) {
        int col = k0 - 1 + i;
        bool cv = (unsigned)col < (unsigned)WP;
        float4 a  = (rv0 && cv) ? __ldg(rowA + (size_t)col * CV4) : z;
        float4 bb = (rv1 && cv) ? __ldg(rowB + (size_t)col * CV4) : z;
        T[i] = blend2(a, wr0, bb, fr);
    }

    float4* op = out4 + (((size_t)b * HIN + y) * WIN + k0 * 4) * CV4 + c4;

    if (kk >= 1 && kk <= 30) {
        op[0 * CV4] = blend2(T[0], 0.375f, T[1], 0.625f);
        op[1 * CV4] = blend2(T[0], 0.125f, T[1], 0.875f);
        op[2 * CV4] = blend2(T[1], 0.875f, T[2], 0.125f);
        op[3 * CV4] = blend2(T[1], 0.625f, T[2], 0.375f);
        op[4 * CV4] = blend2(T[1], 0.375f, T[2], 0.625f);
        op[5 * CV4] = blend2(T[1], 0.125f, T[2], 0.875f);
        op[6 * CV4] = blend2(T[2], 0.875f, T[3], 0.125f);
        op[7 * CV4] = blend2(T[2], 0.625f, T[3], 0.375f);
    } else {
        int x0 = k0 * 4;
        #pragma unroll
        for (int m = 0; m < 8; ++m) {
            float sc  = d2s((float)(x0 + m));
            float c0f = floorf(sc);
            float fc  = sc - c0f;
            int idx = (int)c0f - (k0 - 1);   // 0..2
            float4 lo = (idx == 0) ? T[0] : ((idx == 1) ? T[1] : T[2]);
            float4 hi = (idx == 0) ? T[1] : ((idx == 1) ? T[2] : T[3]);
            op[m * CV4] = blend2(lo, 1.0f - fc, hi, fc);
        }
    }
}

extern "C" void kernel_launch(void* const* d_in, const int* in_sizes, int n_in,
                              void* d_out, int out_size) {
    const float4* in4 = (const float4*)d_in[0];
    float4* out4 = (float4*)d_out;

    pool_kernel<<<B * HP * 16, 288>>>(in4);               // 8192 CTAs
    up_kernel<<<(B * HIN * 32 * CV4) / 256, 256>>>(out4); // 4096 CTAs
}